// round 1
// baseline (speedup 1.0000x reference)
#include <cuda_runtime.h>

#define THETA 0.7f

// Precomputed effective weights, layout [cin][tap][oc] for contiguous per-(cin,tap) oc vectors.
__device__ float g_Wp[64 * 9 * 64];

__global__ void prep_w_kernel(const float* __restrict__ W) {
    int idx = blockIdx.x * blockDim.x + threadIdx.x;
    if (idx >= 64 * 64 * 9) return;
    int oc  = idx / 576;
    int rem = idx % 576;
    int cin = rem / 9;
    int tap = rem % 9;
    const float* base = W + oc * 576 + cin * 9;
    float v = base[tap];
    if (tap == 4) {
        float s = 0.f;
#pragma unroll
        for (int t = 0; t < 9; t++) s += base[t];
        v -= THETA * s;
    }
    g_Wp[(cin * 9 + tap) * 64 + oc] = v;
}

__device__ __forceinline__ int refl(int i, int n) {
    if (i < 0) i = -i;
    if (i >= n) i = 2 * n - 2 - i;
    return i;
}

// Block: 16x16 spatial tile x 64 output channels, one batch element.
// 256 threads: ocg = tid&7 (oc = ocg + 8*u), pxg = tid>>3 -> 2x4 pixel patch.
// Per-thread register tile: 8 oc x 8 px = 64 accumulators -> FFMA:LDS = 4:1.
__global__ __launch_bounds__(256, 2)
void conv_kernel(const float* __restrict__ x, float* __restrict__ out) {
    __shared__ float xs[20 * 20];   // raw x tile (reflect-padded indexing)
    __shared__ float ss[18 * 20];   // box3x3 sum tile, zero outside image (conv zero-pad)
    __shared__ float ws[9 * 64];    // weights for current cin: [tap][oc]

    const int tx = blockIdx.x, ty = blockIdx.y, b = blockIdx.z;
    const int tid = threadIdx.x;
    const int ocg = tid & 7;
    const int pxg = tid >> 3;
    const int pr0 = (pxg >> 2) * 2;   // 0..14 step 2
    const int pc0 = (pxg & 3) * 4;    // 0,4,8,12

    const int y0 = ty * 16 - 2;       // x-tile origin (needs rows y0..y0+19)
    const int x0 = tx * 16 - 2;

    float acc[8][8];
#pragma unroll
    for (int i = 0; i < 8; i++)
#pragma unroll
        for (int j = 0; j < 8; j++) acc[i][j] = 0.f;

    for (int cin = 0; cin < 64; cin++) {
        const float* xp = x + (size_t)(b * 64 + cin) * (128 * 128);

        // Load 20x20 x tile with reflect indexing (400 elems / 256 threads).
#pragma unroll
        for (int k = 0; k < 2; k++) {
            int idx = tid + k * 256;
            if (idx < 400) {
                int r = idx / 20, c = idx % 20;
                int gr = refl(y0 + r, 128);
                int gc = refl(x0 + c, 128);
                xs[r * 20 + c] = xp[gr * 128 + gc];
            }
        }
        // Load weights for this cin: 576 floats, coalesced.
        {
            const float* wp = g_Wp + cin * 576;
            ws[tid]       = wp[tid];
            ws[tid + 256] = wp[tid + 256];
            if (tid < 64) ws[tid + 512] = wp[tid + 512];
        }
        __syncthreads();

        // Compute 18x18 s tile (box3x3 of reflect-padded x); zero outside image.
#pragma unroll
        for (int k = 0; k < 2; k++) {
            int idx = tid + k * 256;
            if (idx < 324) {
                int rs = idx / 18, cs = idx % 18;
                int sy = y0 + 1 + rs, sx = x0 + 1 + cs;
                float v = 0.f;
                if (sy >= 0 && sy < 128 && sx >= 0 && sx < 128) {
#pragma unroll
                    for (int d = 0; d < 3; d++)
#pragma unroll
                        for (int e = 0; e < 3; e++)
                            v += xs[(rs + d) * 20 + (cs + e)];
                }
                ss[rs * 20 + cs] = v;
            }
        }
        __syncthreads();

        // 9 taps x (8 oc x 8 px) FMAs.
#pragma unroll
        for (int ky = 0; ky < 3; ky++) {
#pragma unroll
            for (int kx = 0; kx < 3; kx++) {
                const int tap = ky * 3 + kx;
                float wv[8], sv[8];
#pragma unroll
                for (int u = 0; u < 8; u++) wv[u] = ws[tap * 64 + ocg + 8 * u];
#pragma unroll
                for (int r = 0; r < 2; r++)
#pragma unroll
                    for (int c = 0; c < 4; c++)
                        sv[r * 4 + c] = ss[(pr0 + r + ky) * 20 + (pc0 + c + kx)];
#pragma unroll
                for (int u = 0; u < 8; u++)
#pragma unroll
                    for (int p = 0; p < 8; p++)
                        acc[u][p] += wv[u] * sv[p];
            }
        }
        __syncthreads();
    }

    // Epilogue: write 64 values per thread.
#pragma unroll
    for (int u = 0; u < 8; u++) {
        int oc = ocg + 8 * u;
        float* op = out + ((size_t)b * 64 + oc) * (128 * 128);
#pragma unroll
        for (int r = 0; r < 2; r++)
#pragma unroll
            for (int c = 0; c < 4; c++)
                op[(ty * 16 + pr0 + r) * 128 + (tx * 16 + pc0 + c)] = acc[u][r * 4 + c];
    }
}

extern "C" void kernel_launch(void* const* d_in, const int* in_sizes, int n_in,
                              void* d_out, int out_size) {
    const float* x = (const float*)d_in[0];   // [16,64,128,128]
    const float* W = (const float*)d_in[1];   // [64,64,3,3]
    float* out = (float*)d_out;               // [16,64,128,128]

    prep_w_kernel<<<(64 * 64 * 9 + 255) / 256, 256>>>(W);

    dim3 grid(128 / 16, 128 / 16, 16);
    conv_kernel<<<grid, 256>>>(x, out);
}